// round 5
// baseline (speedup 1.0000x reference)
#include <cuda_runtime.h>

typedef unsigned long long u64t;

__device__ __forceinline__ u64t fma2(u64t a, u64t b, u64t c) {
    u64t d;
    asm("fma.rn.f32x2 %0, %1, %2, %3;" : "=l"(d) : "l"(a), "l"(b), "l"(c));
    return d;
}
__device__ __forceinline__ u64t pk2(float lo, float hi) {
    u64t d;
    asm("mov.b64 %0, {%1, %2};" : "=l"(d) : "f"(lo), "f"(hi));
    return d;
}
__device__ __forceinline__ void unpk(u64t v, float& lo, float& hi) {
    asm("mov.b64 {%0, %1}, %2;" : "=f"(lo), "=f"(hi) : "l"(v));
}
__device__ __forceinline__ float fsqrt_ap(float x) {
    float y;
    asm("sqrt.approx.f32 %0, %1;" : "=f"(y) : "f"(x));
    return y;
}

// ---- weight region (u64t units). Each u64 = (w[2p], w[2p+1]) row pair ----
#define OW1 0
#define OW2 4560
#define OW0 6000
#define OB1 6864
#define OB0 7104
#define SM_U64 7107            // 56856 bytes of weights

// ---- stash: 288 features x 128 elements, swizzled (conflict-free R and W) ----
// word index for (feature f, element e):
#define SIDX(f, e) (((f) << 7) + (((e) + ((f) >> 2)) & 127))
#define STASH_WORDS (288 * 128)                       // 147456 B
#define SMEM_BYTES  (SM_U64 * 8 + STASH_WORDS * 4)    // 204312 B

template<int J, int PS, int WS>
__device__ __forceinline__ void do_joint(
    float* __restrict__ stash, int tid, const u64t* __restrict__ sm,
    u64t (&fslot)[4][3], float (&jx)[4], float (&jy)[4], float (&jz)[4],
    const u64t (&g)[3])
{
    float xs[20];
#pragma unroll
    for (int i = 0; i < 9; ++i) xs[i] = stash[SIDX(J*9 + i, tid)];
    float jxv = stash[SIDX(216 + J*3 + 0, tid)];
    float jyv = stash[SIDX(216 + J*3 + 1, tid)];
    float jzv = stash[SIDX(216 + J*3 + 2, tid)];
    xs[9] = jxv; xs[10] = jyv; xs[11] = jzv;

    float dx, dy, dz;
    if (PS < 0) { dx = jxv; dy = jyv; dz = jzv; }
    else {
        const int P = (PS < 0) ? 0 : PS;
        dx = jxv - jx[P]; dy = jyv - jy[P]; dz = jzv - jz[P];
    }
    xs[12] = fsqrt_ap(dx*dx + dy*dy + dz*dz);
    jx[WS] = jxv; jy[WS] = jyv; jz[WS] = jzv;

    if (PS < 0) {
        unpk(g[0], xs[13], xs[14]); unpk(g[1], xs[15], xs[16]); unpk(g[2], xs[17], xs[18]);
    } else {
        const int P = (PS < 0) ? 0 : PS;
        unpk(fslot[P][0], xs[13], xs[14]);
        unpk(fslot[P][1], xs[15], xs[16]);
        unpk(fslot[P][2], xs[17], xs[18]);
    }
    xs[19] = 0.f;

    // layer 1 with rotating weight double-buffer (prefetch k+1 under k's FMAs)
    u64t h[10];
    {
        const ulonglong2* bb = (const ulonglong2*)(sm + OB1 + J*10);
#pragma unroll
        for (int r = 0; r < 5; ++r) { ulonglong2 t = bb[r]; h[2*r] = t.x; h[2*r+1] = t.y; }
    }
    const ulonglong2* wb = (const ulonglong2*)(sm + OW1 + (J*19)*10);
    ulonglong2 wa0 = wb[0], wa1 = wb[1], wa2 = wb[2], wa3 = wb[3], wa4 = wb[4];
#pragma unroll
    for (int k = 0; k < 19; ++k) {
        ulonglong2 wn0, wn1, wn2, wn3, wn4;
        if (k < 18) {
            const ulonglong2* nx = wb + (k + 1)*5;
            wn0 = nx[0]; wn1 = nx[1]; wn2 = nx[2]; wn3 = nx[3]; wn4 = nx[4];
        }
        u64t xx = pk2(xs[k], xs[k]);
        h[0] = fma2(xx, wa0.x, h[0]);
        h[1] = fma2(xx, wa0.y, h[1]);
        h[2] = fma2(xx, wa1.x, h[2]);
        h[3] = fma2(xx, wa1.y, h[3]);
        h[4] = fma2(xx, wa2.x, h[4]);
        h[5] = fma2(xx, wa2.y, h[5]);
        h[6] = fma2(xx, wa3.x, h[6]);
        h[7] = fma2(xx, wa3.y, h[7]);
        h[8] = fma2(xx, wa4.x, h[8]);
        h[9] = fma2(xx, wa4.y, h[9]);
        if (k < 18) { wa0 = wn0; wa1 = wn1; wa2 = wn2; wa3 = wn3; wa4 = wn4; }
    }

    float hs[20];
#pragma unroll
    for (int r = 0; r < 10; ++r) {
        float a, b; unpk(h[r], a, b);
        hs[2*r]   = fmaxf(a, 0.f);
        hs[2*r+1] = fmaxf(b, 0.f);
    }
    hs[19] = 1.0f;   // feeds b2 row (k=19) of sW2

    // layer 2: o (3 d-pairs) = W2[j] @ h (+ b2 via k=19 row)
    u64t o[3];
    o[0] = 0ull; o[1] = 0ull; o[2] = 0ull;
#pragma unroll
    for (int kp = 0; kp < 10; ++kp) {
        const int k0 = 2*kp;
        const ulonglong2* wp = (const ulonglong2*)(sm + OW2 + (J*20 + k0)*3);
        ulonglong2 p0 = wp[0], p1 = wp[1], p2 = wp[2];
        u64t x0 = pk2(hs[k0], hs[k0]);
        u64t x1 = pk2(hs[k0+1], hs[k0+1]);
        o[0] = fma2(x0, p0.x, o[0]);
        o[1] = fma2(x0, p0.y, o[1]);
        o[2] = fma2(x0, p1.x, o[2]);
        o[0] = fma2(x1, p1.y, o[0]);
        o[1] = fma2(x1, p2.x, o[1]);
        o[2] = fma2(x1, p2.y, o[2]);
    }

    fslot[WS][0] = o[0]; fslot[WS][1] = o[1]; fslot[WS][2] = o[2];

    // write outputs into the just-freed rot slots (f = 9J .. 9J+5) of this thread's column
    float v0, v1, v2, v3, v4, v5;
    unpk(o[0], v0, v1); unpk(o[1], v2, v3); unpk(o[2], v4, v5);
    stash[SIDX(9*J + 0, tid)] = v0;
    stash[SIDX(9*J + 1, tid)] = v1;
    stash[SIDX(9*J + 2, tid)] = v2;
    stash[SIDX(9*J + 3, tid)] = v3;
    stash[SIDX(9*J + 4, tid)] = v4;
    stash[SIDX(9*J + 5, tid)] = v5;
}

__global__ void __launch_bounds__(128, 1)
pose_kernel(const float* __restrict__ rots, const float* __restrict__ jtrs,
            const float* __restrict__ W0, const float* __restrict__ b0,
            const float* __restrict__ W1, const float* __restrict__ b1,
            const float* __restrict__ W2, const float* __restrict__ b2,
            float* __restrict__ out)
{
    extern __shared__ u64t sm[];
    float* stash = (float*)(sm + SM_U64);
    const int tid = threadIdx.x;

    // ---- staging: coalesced LDG.128, conflict-free swizzled STS ----
    {
        const float4* gr4 = (const float4*)(rots + (size_t)blockIdx.x * 128 * 216);
        const float4* gt4 = (const float4*)(jtrs + (size_t)blockIdx.x * 128 * 72);
#pragma unroll 6
        for (int i = 0; i < 54; ++i) {                  // rots: 6912 float4
            int G = i*128 + tid;
            float4 v = gr4[G];
            int e = G / 54, f4 = G % 54;
            int base = (4*f4)*128 + ((e + f4) & 127);   // SIDX(4*f4, e)
            stash[base      ] = v.x;
            stash[base + 128] = v.y;
            stash[base + 256] = v.z;
            stash[base + 384] = v.w;
        }
#pragma unroll 6
        for (int i = 0; i < 18; ++i) {                  // jtrs: 2304 float4
            int G = i*128 + tid;
            float4 v = gt4[G];
            int e = G / 18, f4 = G % 18;
            int base = (216 + 4*f4)*128 + ((e + 54 + f4) & 127);  // SIDX(216+4*f4, e)
            stash[base      ] = v.x;
            stash[base + 128] = v.y;
            stash[base + 256] = v.z;
            stash[base + 384] = v.w;
        }
    }

    // ---- weight packing (overlaps staging stores) ----
    for (int i = tid; i < 24*19*10; i += 128) {
        int rp = i % 10; int t = i / 10; int k = t % 19; int j = t / 19;
        int r = 2*rp;
        float lo = W1[(j*19 + r)*19 + k];
        float hi = (r + 1 < 19) ? W1[(j*19 + r + 1)*19 + k] : 0.f;
        sm[OW1 + i] = pk2(lo, hi);
    }
    for (int i = tid; i < 24*20*3; i += 128) {
        int dp = i % 3; int t = i / 3; int k = t % 20; int j = t / 20;
        float lo, hi;
        if (k < 19) { lo = W2[(j*6 + 2*dp)*19 + k]; hi = W2[(j*6 + 2*dp + 1)*19 + k]; }
        else        { lo = b2[j*6 + 2*dp];          hi = b2[j*6 + 2*dp + 1]; }
        sm[OW2 + i] = pk2(lo, hi);
    }
    for (int i = tid; i < 288*3; i += 128) {
        int dp = i % 3; int k = i / 3;
        sm[OW0 + i] = pk2(W0[(2*dp)*288 + k], W0[(2*dp + 1)*288 + k]);
    }
    for (int i = tid; i < 24*10; i += 128) {
        int rp = i % 10; int j = i / 10;
        int r = 2*rp;
        float lo = b1[j*19 + r];
        float hi = (r + 1 < 19) ? b1[j*19 + r + 1] : 0.f;
        sm[OB1 + i] = pk2(lo, hi);
    }
    if (tid < 3) sm[OB0 + tid] = pk2(b0[2*tid], b0[2*tid + 1]);
    __syncthreads();

    // ---- pass 1: gfeat = W0 @ x + b0 (conflict-free LDS from stash) ----
    u64t g[3];
    g[0] = sm[OB0 + 0]; g[1] = sm[OB0 + 1]; g[2] = sm[OB0 + 2];
#pragma unroll 8
    for (int kp = 0; kp < 144; ++kp) {
        int k0 = 2*kp;
        float v0 = stash[SIDX(k0,     tid)];
        float v1 = stash[SIDX(k0 + 1, tid)];
        const ulonglong2* wp = (const ulonglong2*)(sm + OW0 + k0*3);
        ulonglong2 p0 = wp[0], p1 = wp[1], p2 = wp[2];
        u64t x0 = pk2(v0, v0);
        u64t x1 = pk2(v1, v1);
        g[0] = fma2(x0, p0.x, g[0]);
        g[1] = fma2(x0, p0.y, g[1]);
        g[2] = fma2(x0, p1.x, g[2]);
        g[0] = fma2(x1, p1.y, g[0]);
        g[1] = fma2(x1, p2.x, g[1]);
        g[2] = fma2(x1, p2.y, g[2]);
    }

    // ---- pass 2: joint chain (outputs land in freed stash slots) ----
    u64t fslot[4][3];
    float jx[4], jy[4], jz[4];

    do_joint< 0,-1,0>(stash, tid, sm, fslot, jx, jy, jz, g);
    do_joint< 1, 0,1>(stash, tid, sm, fslot, jx, jy, jz, g);
    do_joint< 2, 0,2>(stash, tid, sm, fslot, jx, jy, jz, g);
    do_joint< 3, 0,3>(stash, tid, sm, fslot, jx, jy, jz, g);
    do_joint< 4, 1,0>(stash, tid, sm, fslot, jx, jy, jz, g);
    do_joint< 5, 2,1>(stash, tid, sm, fslot, jx, jy, jz, g);
    do_joint< 6, 3,2>(stash, tid, sm, fslot, jx, jy, jz, g);
    do_joint< 7, 0,3>(stash, tid, sm, fslot, jx, jy, jz, g);
    do_joint< 8, 1,0>(stash, tid, sm, fslot, jx, jy, jz, g);
    do_joint< 9, 2,1>(stash, tid, sm, fslot, jx, jy, jz, g);
    do_joint<10, 3,2>(stash, tid, sm, fslot, jx, jy, jz, g);
    do_joint<11, 0,2>(stash, tid, sm, fslot, jx, jy, jz, g);
    do_joint<12, 1,2>(stash, tid, sm, fslot, jx, jy, jz, g);
    do_joint<13, 1,0>(stash, tid, sm, fslot, jx, jy, jz, g);
    do_joint<14, 1,3>(stash, tid, sm, fslot, jx, jy, jz, g);
    do_joint<15, 2,1>(stash, tid, sm, fslot, jx, jy, jz, g);
    do_joint<16, 0,1>(stash, tid, sm, fslot, jx, jy, jz, g);
    do_joint<17, 3,0>(stash, tid, sm, fslot, jx, jy, jz, g);
    do_joint<18, 1,3>(stash, tid, sm, fslot, jx, jy, jz, g);
    do_joint<19, 0,1>(stash, tid, sm, fslot, jx, jy, jz, g);
    do_joint<20, 3,0>(stash, tid, sm, fslot, jx, jy, jz, g);
    do_joint<21, 1,3>(stash, tid, sm, fslot, jx, jy, jz, g);
    do_joint<22, 0,1>(stash, tid, sm, fslot, jx, jy, jz, g);
    do_joint<23, 3,0>(stash, tid, sm, fslot, jx, jy, jz, g);

    // ---- epilogue: coalesced store of all 128 x 144 outputs ----
    __syncthreads();
    float* og = out + (size_t)blockIdx.x * (128 * 144);
#pragma unroll 8
    for (int i = 0; i < 144; ++i) {
        int G = i*128 + tid;
        int e = G / 144, fo = G % 144;
        int J = fo / 6, c = fo % 6;
        og[G] = stash[SIDX(9*J + c, e)];
    }
}

extern "C" void kernel_launch(void* const* d_in, const int* in_sizes, int n_in,
                              void* d_out, int out_size) {
    (void)n_in; (void)out_size;
    const float* rots = (const float*)d_in[0];
    const float* jtrs = (const float*)d_in[1];
    const float* W0   = (const float*)d_in[2];
    const float* b0   = (const float*)d_in[3];
    const float* W1   = (const float*)d_in[4];
    const float* b1   = (const float*)d_in[5];
    const float* W2   = (const float*)d_in[6];
    const float* b2   = (const float*)d_in[7];
    float* out = (float*)d_out;

    int n = in_sizes[0] / 216;        // B (131072 -> divisible by 128)
    int grid = n / 128;

    cudaFuncSetAttribute(pose_kernel, cudaFuncAttributeMaxDynamicSharedMemorySize, SMEM_BYTES);
    pose_kernel<<<grid, 128, SMEM_BYTES>>>(rots, jtrs, W0, b0, W1, b1, W2, b2, out);
}

// round 6
// speedup vs baseline: 1.3894x; 1.3894x over previous
#include <cuda_runtime.h>

typedef unsigned long long u64t;

__device__ __forceinline__ u64t fma2(u64t a, u64t b, u64t c) {
    u64t d;
    asm("fma.rn.f32x2 %0, %1, %2, %3;" : "=l"(d) : "l"(a), "l"(b), "l"(c));
    return d;
}
__device__ __forceinline__ u64t add2(u64t a, u64t b) {
    u64t d;
    asm("add.rn.f32x2 %0, %1, %2;" : "=l"(d) : "l"(a), "l"(b));
    return d;
}
__device__ __forceinline__ u64t pk2(float lo, float hi) {
    u64t d;
    asm("mov.b64 %0, {%1, %2};" : "=l"(d) : "f"(lo), "f"(hi));
    return d;
}
__device__ __forceinline__ void unpk(u64t v, float& lo, float& hi) {
    asm("mov.b64 {%0, %1}, %2;" : "=f"(lo), "=f"(hi) : "l"(v));
}
__device__ __forceinline__ float fsqrt_ap(float x) {
    float y;
    asm("sqrt.approx.f32 %0, %1;" : "=f"(y) : "f"(x));
    return y;
}
// xor-1 exchange of a u64 (pair partner is in-warp)
__device__ __forceinline__ u64t shx1(u64t v) {
    unsigned lo = (unsigned)v, hi = (unsigned)(v >> 32);
    lo = __shfl_xor_sync(0xffffffffu, lo, 1);
    hi = __shfl_xor_sync(0xffffffffu, hi, 1);
    return ((u64t)hi << 32) | lo;
}

// ---- weight region (u64t units) ----
// sW1: [24][19 k][12]: slots 0..4 = row-pairs 0..4 (rows 0..9), slot 5 pad,
//                      slots 6..10 = row-pairs 5..9 (rows 10..19, pair 9 hi = 0 pad), slot 11 pad
// sW2: [24][20 k][3 dp]  (k=19 row = b2; fed by hs==1 on odd lane)
// sW0: [288 k][3 dp]
// sB1: [24][12] (same half scheme as sW1)
// sB0: [3 dp]
#define OW1 0
#define OW2 5472
#define OW0 6912
#define OB1 7776
#define OB0 8064
#define SM_U64 8067            // 64536 bytes of weights

// ---- stash: 288 features x 128 elements, swizzled ----
#define SIDX(f, e) (((f) << 7) + (((e) + ((f) >> 2)) & 127))
#define STASH_WORDS (288 * 128)                       // 147456 B
#define SMEM_BYTES  (SM_U64 * 8 + STASH_WORDS * 4)    // 211992 B

template<int J, int PS, int WS>
__device__ __forceinline__ void do_joint(
    float* __restrict__ stash, int e, int half, const u64t* __restrict__ sm,
    u64t (&fslot)[4][3], float (&jx)[4], float (&jy)[4], float (&jz)[4],
    const u64t (&g)[3])
{
    float xs[19];
#pragma unroll
    for (int i = 0; i < 9; ++i) xs[i] = stash[SIDX(J*9 + i, e)];
    float jxv = stash[SIDX(216 + J*3 + 0, e)];
    float jyv = stash[SIDX(216 + J*3 + 1, e)];
    float jzv = stash[SIDX(216 + J*3 + 2, e)];
    xs[9] = jxv; xs[10] = jyv; xs[11] = jzv;

    float dx, dy, dz;
    if (PS < 0) { dx = jxv; dy = jyv; dz = jzv; }
    else {
        const int P = (PS < 0) ? 0 : PS;
        dx = jxv - jx[P]; dy = jyv - jy[P]; dz = jzv - jz[P];
    }
    xs[12] = fsqrt_ap(dx*dx + dy*dy + dz*dz);
    jx[WS] = jxv; jy[WS] = jyv; jz[WS] = jzv;

    if (PS < 0) {
        unpk(g[0], xs[13], xs[14]); unpk(g[1], xs[15], xs[16]); unpk(g[2], xs[17], xs[18]);
    } else {
        const int P = (PS < 0) ? 0 : PS;
        unpk(fslot[P][0], xs[13], xs[14]);
        unpk(fslot[P][1], xs[15], xs[16]);
        unpk(fslot[P][2], xs[17], xs[18]);
    }

    // ---- layer 1, this lane's half: 5 row-pair chains (rows 10*half .. 10*half+9) ----
    u64t hh[5];
    {
        const u64t* bb = sm + OB1 + J*12 + half*6;
        ulonglong2 t0 = *(const ulonglong2*)bb;
        ulonglong2 t1 = *(const ulonglong2*)(bb + 2);
        hh[0] = t0.x; hh[1] = t0.y; hh[2] = t1.x; hh[3] = t1.y; hh[4] = bb[4];
    }
    const u64t* wb = sm + OW1 + (J*19)*12 + half*6;
#pragma unroll
    for (int k = 0; k < 19; ++k) {
        const u64t* wr = wb + k*12;
        ulonglong2 w0 = *(const ulonglong2*)wr;
        ulonglong2 w1 = *(const ulonglong2*)(wr + 2);
        u64t w4 = wr[4];
        u64t xx = pk2(xs[k], xs[k]);
        hh[0] = fma2(xx, w0.x, hh[0]);
        hh[1] = fma2(xx, w0.y, hh[1]);
        hh[2] = fma2(xx, w1.x, hh[2]);
        hh[3] = fma2(xx, w1.y, hh[3]);
        hh[4] = fma2(xx, w4,   hh[4]);
    }

    float hs[10];
#pragma unroll
    for (int r = 0; r < 5; ++r) {
        float a, b; unpk(hh[r], a, b);
        hs[2*r]   = fmaxf(a, 0.f);
        hs[2*r+1] = fmaxf(b, 0.f);
    }
    if (half) hs[9] = 1.0f;   // row 19 pad -> feeds b2 row (k=19) of sW2

    // ---- layer 2 partial over this lane's k half ----
    u64t o0 = 0ull, o1 = 0ull, o2 = 0ull;
#pragma unroll
    for (int i = 0; i < 5; ++i) {
        int k0 = 2*(half*5 + i);
        const ulonglong2* wp = (const ulonglong2*)(sm + OW2 + (J*20 + k0)*3);
        ulonglong2 p0 = wp[0], p1 = wp[1], p2 = wp[2];
        u64t x0 = pk2(hs[2*i],   hs[2*i]);
        u64t x1 = pk2(hs[2*i+1], hs[2*i+1]);
        o0 = fma2(x0, p0.x, o0);
        o1 = fma2(x0, p0.y, o1);
        o2 = fma2(x0, p1.x, o2);
        o0 = fma2(x1, p1.y, o0);
        o1 = fma2(x1, p2.x, o1);
        o2 = fma2(x1, p2.y, o2);
    }
    // combine halves (lane pair is xor-1 within warp)
    o0 = add2(o0, shx1(o0));
    o1 = add2(o1, shx1(o1));
    o2 = add2(o2, shx1(o2));

    fslot[WS][0] = o0; fslot[WS][1] = o1; fslot[WS][2] = o2;

    // write this lane's 3 output components into freed rot slots f = 9J+3*half ..
    float v0, v1, v2, v3, v4, v5;
    unpk(o0, v0, v1); unpk(o1, v2, v3); unpk(o2, v4, v5);
    float w0 = half ? v3 : v0;
    float w1 = half ? v4 : v1;
    float w2 = half ? v5 : v2;
    int c0 = 9*J + 3*half;
    stash[SIDX(c0 + 0, e)] = w0;
    stash[SIDX(c0 + 1, e)] = w1;
    stash[SIDX(c0 + 2, e)] = w2;
}

__global__ void __launch_bounds__(256, 1)
pose_kernel(const float* __restrict__ rots, const float* __restrict__ jtrs,
            const float* __restrict__ W0, const float* __restrict__ b0,
            const float* __restrict__ W1, const float* __restrict__ b1,
            const float* __restrict__ W2, const float* __restrict__ b2,
            float* __restrict__ out)
{
    extern __shared__ u64t sm[];
    float* stash = (float*)(sm + SM_U64);
    const int tid = threadIdx.x;

    // ---- staging: coalesced LDG.128 -> conflict-free swizzled STS ----
    {
        const float4* gr4 = (const float4*)(rots + (size_t)blockIdx.x * 128 * 216);
        const float4* gt4 = (const float4*)(jtrs + (size_t)blockIdx.x * 128 * 72);
#pragma unroll 3
        for (int i = 0; i < 27; ++i) {                  // rots: 6912 float4
            int G = i*256 + tid;
            float4 v = gr4[G];
            int e = G / 54, f4 = G % 54;
            int base = (4*f4)*128 + ((e + f4) & 127);   // SIDX(4*f4, e)
            stash[base      ] = v.x;
            stash[base + 128] = v.y;
            stash[base + 256] = v.z;
            stash[base + 384] = v.w;
        }
#pragma unroll 3
        for (int i = 0; i < 9; ++i) {                   // jtrs: 2304 float4
            int G = i*256 + tid;
            float4 v = gt4[G];
            int e = G / 18, f4 = G % 18;
            int base = (216 + 4*f4)*128 + ((e + 54 + f4) & 127);  // SIDX(216+4*f4, e)
            stash[base      ] = v.x;
            stash[base + 128] = v.y;
            stash[base + 256] = v.z;
            stash[base + 384] = v.w;
        }
    }

    // ---- weight packing ----
    for (int i = tid; i < 24*19*12; i += 256) {
        int s = i % 12; int t = i / 12; int k = t % 19; int j = t / 19;
        float lo = 0.f, hi = 0.f;
        int p = (s < 6) ? s : (s - 6 + 5);     // slot -> row pair (5 = pad slot)
        if (s != 5 && s != 11) {
            int r = 2*p;
            lo = W1[(j*19 + r)*19 + k];
            hi = (r + 1 < 19) ? W1[(j*19 + r + 1)*19 + k] : 0.f;
        }
        sm[OW1 + i] = pk2(lo, hi);
    }
    for (int i = tid; i < 24*20*3; i += 256) {
        int dp = i % 3; int t = i / 3; int k = t % 20; int j = t / 20;
        float lo, hi;
        if (k < 19) { lo = W2[(j*6 + 2*dp)*19 + k]; hi = W2[(j*6 + 2*dp + 1)*19 + k]; }
        else        { lo = b2[j*6 + 2*dp];          hi = b2[j*6 + 2*dp + 1]; }
        sm[OW2 + i] = pk2(lo, hi);
    }
    for (int i = tid; i < 288*3; i += 256) {
        int dp = i % 3; int k = i / 3;
        sm[OW0 + i] = pk2(W0[(2*dp)*288 + k], W0[(2*dp + 1)*288 + k]);
    }
    for (int i = tid; i < 24*12; i += 256) {
        int s = i % 12; int j = i / 12;
        float lo = 0.f, hi = 0.f;
        int p = (s < 6) ? s : (s - 6 + 5);
        if (s != 5 && s != 11) {
            int r = 2*p;
            lo = b1[j*19 + r];
            hi = (r + 1 < 19) ? b1[j*19 + r + 1] : 0.f;
        }
        sm[OB1 + i] = pk2(lo, hi);
    }
    if (tid < 3) sm[OB0 + tid] = pk2(b0[2*tid], b0[2*tid + 1]);
    __syncthreads();

    const int e    = tid >> 1;     // element owned by this lane pair
    const int half = tid & 1;      // 0: rows/k 0..9(,0..143)  1: rows/k 10..19(,144..287)

    // ---- pass 1: gfeat partial over this lane's k half, then exchange ----
    u64t g[3];
    if (half == 0) { g[0] = sm[OB0 + 0]; g[1] = sm[OB0 + 1]; g[2] = sm[OB0 + 2]; }
    else           { g[0] = 0ull;        g[1] = 0ull;        g[2] = 0ull; }
    {
        const int koff = half * 144;
#pragma unroll 6
        for (int kp = 0; kp < 72; ++kp) {
            int k0 = koff + 2*kp;
            float v0 = stash[SIDX(k0,     e)];
            float v1 = stash[SIDX(k0 + 1, e)];
            const ulonglong2* wp = (const ulonglong2*)(sm + OW0 + k0*3);
            ulonglong2 p0 = wp[0], p1 = wp[1], p2 = wp[2];
            u64t x0 = pk2(v0, v0);
            u64t x1 = pk2(v1, v1);
            g[0] = fma2(x0, p0.x, g[0]);
            g[1] = fma2(x0, p0.y, g[1]);
            g[2] = fma2(x0, p1.x, g[2]);
            g[0] = fma2(x1, p1.y, g[0]);
            g[1] = fma2(x1, p2.x, g[1]);
            g[2] = fma2(x1, p2.y, g[2]);
        }
    }
    g[0] = add2(g[0], shx1(g[0]));
    g[1] = add2(g[1], shx1(g[1]));
    g[2] = add2(g[2], shx1(g[2]));

    // ---- pass 2: joint chain ----
    u64t fslot[4][3];
    float jx[4], jy[4], jz[4];

    do_joint< 0,-1,0>(stash, e, half, sm, fslot, jx, jy, jz, g);
    do_joint< 1, 0,1>(stash, e, half, sm, fslot, jx, jy, jz, g);
    do_joint< 2, 0,2>(stash, e, half, sm, fslot, jx, jy, jz, g);
    do_joint< 3, 0,3>(stash, e, half, sm, fslot, jx, jy, jz, g);
    do_joint< 4, 1,0>(stash, e, half, sm, fslot, jx, jy, jz, g);
    do_joint< 5, 2,1>(stash, e, half, sm, fslot, jx, jy, jz, g);
    do_joint< 6, 3,2>(stash, e, half, sm, fslot, jx, jy, jz, g);
    do_joint< 7, 0,3>(stash, e, half, sm, fslot, jx, jy, jz, g);
    do_joint< 8, 1,0>(stash, e, half, sm, fslot, jx, jy, jz, g);
    do_joint< 9, 2,1>(stash, e, half, sm, fslot, jx, jy, jz, g);
    do_joint<10, 3,2>(stash, e, half, sm, fslot, jx, jy, jz, g);
    do_joint<11, 0,2>(stash, e, half, sm, fslot, jx, jy, jz, g);
    do_joint<12, 1,2>(stash, e, half, sm, fslot, jx, jy, jz, g);
    do_joint<13, 1,0>(stash, e, half, sm, fslot, jx, jy, jz, g);
    do_joint<14, 1,3>(stash, e, half, sm, fslot, jx, jy, jz, g);
    do_joint<15, 2,1>(stash, e, half, sm, fslot, jx, jy, jz, g);
    do_joint<16, 0,1>(stash, e, half, sm, fslot, jx, jy, jz, g);
    do_joint<17, 3,0>(stash, e, half, sm, fslot, jx, jy, jz, g);
    do_joint<18, 1,3>(stash, e, half, sm, fslot, jx, jy, jz, g);
    do_joint<19, 0,1>(stash, e, half, sm, fslot, jx, jy, jz, g);
    do_joint<20, 3,0>(stash, e, half, sm, fslot, jx, jy, jz, g);
    do_joint<21, 1,3>(stash, e, half, sm, fslot, jx, jy, jz, g);
    do_joint<22, 0,1>(stash, e, half, sm, fslot, jx, jy, jz, g);
    do_joint<23, 3,0>(stash, e, half, sm, fslot, jx, jy, jz, g);

    // ---- epilogue: coalesced store of all 128 x 144 outputs ----
    __syncthreads();
    float* og = out + (size_t)blockIdx.x * (128 * 144);
#pragma unroll 8
    for (int i = 0; i < 72; ++i) {
        int G = i*256 + tid;
        int ee = G / 144, fo = G % 144;
        int J = fo / 6, c = fo % 6;
        og[G] = stash[SIDX(9*J + c, ee)];
    }
}

extern "C" void kernel_launch(void* const* d_in, const int* in_sizes, int n_in,
                              void* d_out, int out_size) {
    (void)n_in; (void)out_size;
    const float* rots = (const float*)d_in[0];
    const float* jtrs = (const float*)d_in[1];
    const float* W0   = (const float*)d_in[2];
    const float* b0   = (const float*)d_in[3];
    const float* W1   = (const float*)d_in[4];
    const float* b1   = (const float*)d_in[5];
    const float* W2   = (const float*)d_in[6];
    const float* b2   = (const float*)d_in[7];
    float* out = (float*)d_out;

    int n = in_sizes[0] / 216;        // B (131072 -> divisible by 128)
    int grid = n / 128;

    cudaFuncSetAttribute(pose_kernel, cudaFuncAttributeMaxDynamicSharedMemorySize, SMEM_BYTES);
    pose_kernel<<<grid, 256, SMEM_BYTES>>>(rots, jtrs, W0, b0, W1, b1, W2, b2, out);
}

// round 7
// speedup vs baseline: 1.4423x; 1.0381x over previous
#include <cuda_runtime.h>

typedef unsigned long long u64t;

__device__ __forceinline__ u64t fma2(u64t a, u64t b, u64t c) {
    u64t d;
    asm("fma.rn.f32x2 %0, %1, %2, %3;" : "=l"(d) : "l"(a), "l"(b), "l"(c));
    return d;
}
__device__ __forceinline__ u64t add2(u64t a, u64t b) {
    u64t d;
    asm("add.rn.f32x2 %0, %1, %2;" : "=l"(d) : "l"(a), "l"(b));
    return d;
}
__device__ __forceinline__ u64t pk2(float lo, float hi) {
    u64t d;
    asm("mov.b64 %0, {%1, %2};" : "=l"(d) : "f"(lo), "f"(hi));
    return d;
}
__device__ __forceinline__ void unpk(u64t v, float& lo, float& hi) {
    asm("mov.b64 {%0, %1}, %2;" : "=f"(lo), "=f"(hi) : "l"(v));
}
__device__ __forceinline__ float fsqrt_ap(float x) {
    float y;
    asm("sqrt.approx.f32 %0, %1;" : "=f"(y) : "f"(x));
    return y;
}
__device__ __forceinline__ u64t shx1(u64t v) {
    unsigned lo = (unsigned)v, hi = (unsigned)(v >> 32);
    lo = __shfl_xor_sync(0xffffffffu, lo, 1);
    hi = __shfl_xor_sync(0xffffffffu, hi, 1);
    return ((u64t)hi << 32) | lo;
}

// ---- weight region (u64t units) ----
// sW1: [24][19 k][12]: slots 0..4 = row-pairs 0..4 (rows 0..9), slot 5 pad,
//                      slots 6..10 = row-pairs 5..9 (pair 9 hi = 0 pad), slot 11 pad
// sW2: [24][20 k][3 dp]  (k=19 row = b2; fed by hs==1 on odd lane)
// sW0: [288 f'][3 dp]    (columns PERMUTED to f' order)
// sB1: [24][12] (same half scheme as sW1)
// sB0: [3 dp]
#define OW1 0
#define OW2 5472
#define OW0 6912
#define OB1 7776
#define OB0 8064
#define SM_U64 8068            // 64544 B (16B-aligned end -> stash aligned)

// ---- stash: element-major, stride 292 floats/element ----
// f' = 12*J + i : i in [0,9) = rot i of joint J ; i in [9,12) = jtr c of joint J
#define ESTRIDE 292
#define STASH_WORDS (128 * ESTRIDE)                   // 149504 B
#define SMEM_BYTES  (SM_U64 * 8 + STASH_WORDS * 4)    // 214048 B

template<int J, int PS, int WS>
__device__ __forceinline__ void do_joint(
    float* __restrict__ se,          // stash + e*ESTRIDE (this lane-pair's element)
    int half, const u64t* __restrict__ sm,
    u64t (&fslot)[4][3], float (&jx)[4], float (&jy)[4], float (&jz)[4],
    const u64t (&g)[3])
{
    // 12 inputs of joint J: one aligned block (immediate offsets off se)
    float xs[19];
    {
        const float4* xb = (const float4*)(se + 12*J);
        float4 a = xb[0], b = xb[1], c = xb[2];
        xs[0]=a.x; xs[1]=a.y; xs[2]=a.z; xs[3]=a.w;
        xs[4]=b.x; xs[5]=b.y; xs[6]=b.z; xs[7]=b.w;
        xs[8]=c.x; xs[9]=c.y; xs[10]=c.z; xs[11]=c.w;
    }
    float jxv = xs[9], jyv = xs[10], jzv = xs[11];

    float dx, dy, dz;
    if (PS < 0) { dx = jxv; dy = jyv; dz = jzv; }
    else {
        const int P = (PS < 0) ? 0 : PS;
        dx = jxv - jx[P]; dy = jyv - jy[P]; dz = jzv - jz[P];
    }
    xs[12] = fsqrt_ap(dx*dx + dy*dy + dz*dz);
    jx[WS] = jxv; jy[WS] = jyv; jz[WS] = jzv;

    if (PS < 0) {
        unpk(g[0], xs[13], xs[14]); unpk(g[1], xs[15], xs[16]); unpk(g[2], xs[17], xs[18]);
    } else {
        const int P = (PS < 0) ? 0 : PS;
        unpk(fslot[P][0], xs[13], xs[14]);
        unpk(fslot[P][1], xs[15], xs[16]);
        unpk(fslot[P][2], xs[17], xs[18]);
    }

    // ---- layer 1, this lane's half: 5 row-pair chains ----
    u64t hh[5];
    {
        const u64t* bb = sm + OB1 + J*12 + half*6;
        ulonglong2 t0 = *(const ulonglong2*)bb;
        ulonglong2 t1 = *(const ulonglong2*)(bb + 2);
        hh[0] = t0.x; hh[1] = t0.y; hh[2] = t1.x; hh[3] = t1.y; hh[4] = bb[4];
    }
    const u64t* wb = sm + OW1 + (J*19)*12 + half*6;
#pragma unroll
    for (int k = 0; k < 19; ++k) {
        const u64t* wr = wb + k*12;
        ulonglong2 w0 = *(const ulonglong2*)wr;
        ulonglong2 w1 = *(const ulonglong2*)(wr + 2);
        u64t w4 = wr[4];
        u64t xx = pk2(xs[k], xs[k]);
        hh[0] = fma2(xx, w0.x, hh[0]);
        hh[1] = fma2(xx, w0.y, hh[1]);
        hh[2] = fma2(xx, w1.x, hh[2]);
        hh[3] = fma2(xx, w1.y, hh[3]);
        hh[4] = fma2(xx, w4,   hh[4]);
    }

    float hs[10];
#pragma unroll
    for (int r = 0; r < 5; ++r) {
        float a, b; unpk(hh[r], a, b);
        hs[2*r]   = fmaxf(a, 0.f);
        hs[2*r+1] = fmaxf(b, 0.f);
    }
    if (half) hs[9] = 1.0f;   // row 19 pad -> feeds b2 row (k=19) of sW2

    // ---- layer 2 partial over this lane's k half ----
    u64t o0 = 0ull, o1 = 0ull, o2 = 0ull;
#pragma unroll
    for (int i = 0; i < 5; ++i) {
        int k0 = 2*(half*5 + i);
        const ulonglong2* wp = (const ulonglong2*)(sm + OW2 + (J*20 + k0)*3);
        ulonglong2 p0 = wp[0], p1 = wp[1], p2 = wp[2];
        u64t x0 = pk2(hs[2*i],   hs[2*i]);
        u64t x1 = pk2(hs[2*i+1], hs[2*i+1]);
        o0 = fma2(x0, p0.x, o0);
        o1 = fma2(x0, p0.y, o1);
        o2 = fma2(x0, p1.x, o2);
        o0 = fma2(x1, p1.y, o0);
        o1 = fma2(x1, p2.x, o1);
        o2 = fma2(x1, p2.y, o2);
    }
    o0 = add2(o0, shx1(o0));
    o1 = add2(o1, shx1(o1));
    o2 = add2(o2, shx1(o2));

    fslot[WS][0] = o0; fslot[WS][1] = o1; fslot[WS][2] = o2;

    // write this lane's 3 output components into freed rot slots f' = 12J + 3*half + c
    float v0, v1, v2, v3, v4, v5;
    unpk(o0, v0, v1); unpk(o1, v2, v3); unpk(o2, v4, v5);
    float w0 = half ? v3 : v0;
    float w1 = half ? v4 : v1;
    float w2 = half ? v5 : v2;
    float* dst = se + 12*J + 3*half;
    dst[0] = w0; dst[1] = w1; dst[2] = w2;
}

__global__ void __launch_bounds__(256, 1)
pose_kernel(const float* __restrict__ rots, const float* __restrict__ jtrs,
            const float* __restrict__ W0, const float* __restrict__ b0,
            const float* __restrict__ W1, const float* __restrict__ b1,
            const float* __restrict__ W2, const float* __restrict__ b2,
            float* __restrict__ out)
{
    extern __shared__ u64t sm[];
    float* stash = (float*)(sm + SM_U64);
    const int tid = threadIdx.x;

    // ---- staging: coalesced LDG.128 -> contiguous (conflict-free) STS ----
    {
        const float4* gr4 = (const float4*)(rots + (size_t)blockIdx.x * 128 * 216);
        const float4* gt4 = (const float4*)(jtrs + (size_t)blockIdx.x * 128 * 72);
#pragma unroll 3
        for (int i = 0; i < 27; ++i) {                  // rots: 6912 float4
            int G = i*256 + tid;
            float4 v = gr4[G];
            int e = G / 54, f4 = G % 54;
            float* dst = stash + e*ESTRIDE;
            int fo = 4*f4;
            float vv[4] = {v.x, v.y, v.z, v.w};
#pragma unroll
            for (int c = 0; c < 4; ++c) {
                int f = fo + c;
                int Jc = f / 9;                         // f' = 12*Jc + (f - 9*Jc) = f + 3*Jc
                dst[f + 3*Jc] = vv[c];
            }
        }
#pragma unroll 3
        for (int i = 0; i < 9; ++i) {                   // jtrs: 2304 float4
            int G = i*256 + tid;
            float4 v = gt4[G];
            int e = G / 18, f4 = G % 18;
            float* dst = stash + e*ESTRIDE;
            int mo = 4*f4;
            float vv[4] = {v.x, v.y, v.z, v.w};
#pragma unroll
            for (int c = 0; c < 4; ++c) {
                int m = mo + c;
                int Jt = m / 3;                         // f' = 12*Jt + 9 + (m - 3*Jt) = m + 9*Jt + 9
                dst[m + 9*Jt + 9] = vv[c];
            }
        }
    }

    // ---- weight packing ----
    for (int i = tid; i < 24*19*12; i += 256) {
        int s = i % 12; int t = i / 12; int k = t % 19; int j = t / 19;
        float lo = 0.f, hi = 0.f;
        int p = (s < 6) ? s : (s - 6 + 5);     // slot -> row pair (5 = pad slot)
        if (s != 5 && s != 11) {
            int r = 2*p;
            lo = W1[(j*19 + r)*19 + k];
            hi = (r + 1 < 19) ? W1[(j*19 + r + 1)*19 + k] : 0.f;
        }
        sm[OW1 + i] = pk2(lo, hi);
    }
    for (int i = tid; i < 24*20*3; i += 256) {
        int dp = i % 3; int t = i / 3; int k = t % 20; int j = t / 20;
        float lo, hi;
        if (k < 19) { lo = W2[(j*6 + 2*dp)*19 + k]; hi = W2[(j*6 + 2*dp + 1)*19 + k]; }
        else        { lo = b2[j*6 + 2*dp];          hi = b2[j*6 + 2*dp + 1]; }
        sm[OW2 + i] = pk2(lo, hi);
    }
    for (int i = tid; i < 288*3; i += 256) {            // W0 columns permuted to f' order
        int dp = i % 3; int fp = i / 3;
        int J = fp / 12, ii = fp % 12;
        int f = (ii < 9) ? (9*J + ii) : (216 + 3*J + (ii - 9));
        sm[OW0 + i] = pk2(W0[(2*dp)*288 + f], W0[(2*dp + 1)*288 + f]);
    }
    for (int i = tid; i < 24*12; i += 256) {
        int s = i % 12; int j = i / 12;
        float lo = 0.f, hi = 0.f;
        int p = (s < 6) ? s : (s - 6 + 5);
        if (s != 5 && s != 11) {
            int r = 2*p;
            lo = b1[j*19 + r];
            hi = (r + 1 < 19) ? b1[j*19 + r + 1] : 0.f;
        }
        sm[OB1 + i] = pk2(lo, hi);
    }
    if (tid < 3) sm[OB0 + tid] = pk2(b0[2*tid], b0[2*tid + 1]);
    __syncthreads();

    const int e    = tid >> 1;     // element owned by this lane pair
    const int half = tid & 1;      // 0: rows/f' 0..; 1: upper half
    float* se = stash + e*ESTRIDE;

    // ---- pass 1: gfeat partial over this lane's f' half, then exchange ----
    u64t g[3];
    if (half == 0) { g[0] = sm[OB0 + 0]; g[1] = sm[OB0 + 1]; g[2] = sm[OB0 + 2]; }
    else           { g[0] = 0ull;        g[1] = 0ull;        g[2] = 0ull; }
    {
        const int koff = half * 144;
        const float4* xb = (const float4*)(se + koff);
#pragma unroll 4
        for (int q = 0; q < 36; ++q) {                  // 4 features per iter
            float4 xv = xb[q];
            float vv[4] = {xv.x, xv.y, xv.z, xv.w};
#pragma unroll
            for (int cp = 0; cp < 2; ++cp) {
                int k0 = koff + 4*q + 2*cp;
                const ulonglong2* wp = (const ulonglong2*)(sm + OW0 + k0*3);
                ulonglong2 p0 = wp[0], p1 = wp[1], p2 = wp[2];
                u64t x0 = pk2(vv[2*cp],   vv[2*cp]);
                u64t x1 = pk2(vv[2*cp+1], vv[2*cp+1]);
                g[0] = fma2(x0, p0.x, g[0]);
                g[1] = fma2(x0, p0.y, g[1]);
                g[2] = fma2(x0, p1.x, g[2]);
                g[0] = fma2(x1, p1.y, g[0]);
                g[1] = fma2(x1, p2.x, g[1]);
                g[2] = fma2(x1, p2.y, g[2]);
            }
        }
    }
    g[0] = add2(g[0], shx1(g[0]));
    g[1] = add2(g[1], shx1(g[1]));
    g[2] = add2(g[2], shx1(g[2]));

    // ---- pass 2: joint chain ----
    u64t fslot[4][3];
    float jx[4], jy[4], jz[4];

    do_joint< 0,-1,0>(se, half, sm, fslot, jx, jy, jz, g);
    do_joint< 1, 0,1>(se, half, sm, fslot, jx, jy, jz, g);
    do_joint< 2, 0,2>(se, half, sm, fslot, jx, jy, jz, g);
    do_joint< 3, 0,3>(se, half, sm, fslot, jx, jy, jz, g);
    do_joint< 4, 1,0>(se, half, sm, fslot, jx, jy, jz, g);
    do_joint< 5, 2,1>(se, half, sm, fslot, jx, jy, jz, g);
    do_joint< 6, 3,2>(se, half, sm, fslot, jx, jy, jz, g);
    do_joint< 7, 0,3>(se, half, sm, fslot, jx, jy, jz, g);
    do_joint< 8, 1,0>(se, half, sm, fslot, jx, jy, jz, g);
    do_joint< 9, 2,1>(se, half, sm, fslot, jx, jy, jz, g);
    do_joint<10, 3,2>(se, half, sm, fslot, jx, jy, jz, g);
    do_joint<11, 0,2>(se, half, sm, fslot, jx, jy, jz, g);
    do_joint<12, 1,2>(se, half, sm, fslot, jx, jy, jz, g);
    do_joint<13, 1,0>(se, half, sm, fslot, jx, jy, jz, g);
    do_joint<14, 1,3>(se, half, sm, fslot, jx, jy, jz, g);
    do_joint<15, 2,1>(se, half, sm, fslot, jx, jy, jz, g);
    do_joint<16, 0,1>(se, half, sm, fslot, jx, jy, jz, g);
    do_joint<17, 3,0>(se, half, sm, fslot, jx, jy, jz, g);
    do_joint<18, 1,3>(se, half, sm, fslot, jx, jy, jz, g);
    do_joint<19, 0,1>(se, half, sm, fslot, jx, jy, jz, g);
    do_joint<20, 3,0>(se, half, sm, fslot, jx, jy, jz, g);
    do_joint<21, 1,3>(se, half, sm, fslot, jx, jy, jz, g);
    do_joint<22, 0,1>(se, half, sm, fslot, jx, jy, jz, g);
    do_joint<23, 3,0>(se, half, sm, fslot, jx, jy, jz, g);

    // ---- epilogue: coalesced store of all 128 x 144 outputs ----
    __syncthreads();
    float* og = out + (size_t)blockIdx.x * (128 * 144);
#pragma unroll 8
    for (int i = 0; i < 72; ++i) {
        int G = i*256 + tid;
        int ee = G / 144, q = G % 144;
        int J = q / 6;                                  // f' = 12J + (q - 6J) = q + 6J
        og[G] = stash[ee*ESTRIDE + q + 6*J];
    }
}

extern "C" void kernel_launch(void* const* d_in, const int* in_sizes, int n_in,
                              void* d_out, int out_size) {
    (void)n_in; (void)out_size;
    const float* rots = (const float*)d_in[0];
    const float* jtrs = (const float*)d_in[1];
    const float* W0   = (const float*)d_in[2];
    const float* b0   = (const float*)d_in[3];
    const float* W1   = (const float*)d_in[4];
    const float* b1   = (const float*)d_in[5];
    const float* W2   = (const float*)d_in[6];
    const float* b2   = (const float*)d_in[7];
    float* out = (float*)d_out;

    int n = in_sizes[0] / 216;        // B (131072 -> divisible by 128)
    int grid = n / 128;

    cudaFuncSetAttribute(pose_kernel, cudaFuncAttributeMaxDynamicSharedMemorySize, SMEM_BYTES);
    pose_kernel<<<grid, 256, SMEM_BYTES>>>(rots, jtrs, W0, b0, W1, b1, W2, b2, out);
}